// round 16
// baseline (speedup 1.0000x reference)
#include <cuda_runtime.h>
#include <cuda.h>
#include <cuda_fp16.h>
#include <cstdint>
#include <cstddef>

// ---------------------------------------------------------------------------
// Problem shape (fixed by dataset)
// ---------------------------------------------------------------------------
static constexpr int Mtot = 8192;   // B*S
static constexpr int Ntot = 4096;   // OUT
static constexpr int Ktot = 4096;   // IN
static constexpr int RANK = 16;

// GEMM tiling: CTA 256x128x64, 8 warps (4Mx2N), warp tile 64x64 (R9 config).
static constexpr int BM = 256;
static constexpr int BN = 128;
static constexpr int BK = 64;               // 64 fp16 = 128B row = SW128 atom
static constexpr int KSTEPS = Ktot / BK;    // 64
static constexpr int STAGES = 4;
static constexpr int NTILES = (Mtot / BM) * (Ntot / BN);   // 32*32 = 1024

static constexpr int A_BYTES = BM * BK * 2;            // 32 KB
static constexpr int B_BYTES = BN * BK * 2;            // 16 KB
static constexpr int STAGE_BYTES = A_BYTES + B_BYTES;  // 48 KB
static constexpr int SMEM_ALLOC = 2048 + STAGES * STAGE_BYTES;  // 198656 B

// fp16 scratch: W' = W + down@up, and x converted
__device__ __align__(1024) __half g_wh[(size_t)Ntot * Ktot];
__device__ __align__(1024) __half g_xh[(size_t)Mtot * Ktot];

// ---------------------------------------------------------------------------
// PTX helpers (non-'a' instructions only: sm_90 TMA + sm_80 mma)
// ---------------------------------------------------------------------------
__device__ __forceinline__ uint32_t s2u(const void* p) {
    uint32_t a;
    asm("{ .reg .u64 t; cvta.to.shared.u64 t, %1; cvt.u32.u64 %0, t; }"
        : "=r"(a) : "l"(p));
    return a;
}

#define MBAR_INIT(addr, cnt) \
    asm volatile("mbarrier.init.shared.b64 [%0], %1;" :: "r"(addr), "r"(cnt) : "memory")

#define MBAR_EXPECT_TX(addr, bytes) \
    asm volatile("mbarrier.arrive.expect_tx.shared.b64 _, [%0], %1;" \
                 :: "r"(addr), "r"(bytes) : "memory")

#define MBAR_ARRIVE(addr) \
    asm volatile("mbarrier.arrive.shared.b64 _, [%0];" :: "r"(addr) : "memory")

#define MBAR_WAIT(addr, parity) do {                                          \
    uint32_t _mb = (addr); uint32_t _ph = (parity); uint32_t _done;           \
    asm volatile("{\n\t.reg .pred p;\n\t"                                     \
        "mbarrier.try_wait.parity.acquire.cta.shared::cta.b64 p, [%1], %2;\n\t" \
        "selp.b32 %0, 1, 0, p;\n\t}"                                          \
        : "=r"(_done) : "r"(_mb), "r"(_ph) : "memory");                       \
    if (!_done) {                                                             \
        asm volatile("{\n\t.reg .pred P1;\n\t"                                \
            "WL_%=:\n\t"                                                      \
            "mbarrier.try_wait.parity.acquire.cta.shared::cta.b64 P1, [%0], %1, 0x989680;\n\t" \
            "@P1 bra.uni WD_%=;\n\t"                                          \
            "bra.uni WL_%=;\n\t"                                              \
            "WD_%=:\n\t}" :: "r"(_mb), "r"(_ph) : "memory");                  \
    }                                                                         \
} while (0)

#define TMA2D(dst, map, cx, cy, mbar)                                         \
    asm volatile("cp.async.bulk.tensor.2d.shared::cta.global.tile"            \
                 ".mbarrier::complete_tx::bytes [%0], [%1, {%2, %3}], [%4];"  \
                 :: "r"(dst), "l"(map), "r"(cx), "r"(cy), "r"(mbar) : "memory")

__device__ __forceinline__ void ldsm4(uint32_t* r, uint32_t addr) {
    asm volatile("ldmatrix.sync.aligned.m8n8.x4.shared.b16 {%0,%1,%2,%3}, [%4];"
                 : "=r"(r[0]), "=r"(r[1]), "=r"(r[2]), "=r"(r[3]) : "r"(addr));
}

__device__ __forceinline__ void mma16816(float* c, const uint32_t* a, const uint32_t* b) {
    asm volatile(
        "mma.sync.aligned.m16n8k16.row.col.f32.f16.f16.f32 "
        "{%0,%1,%2,%3}, {%4,%5,%6,%7}, {%8,%9}, {%0,%1,%2,%3};"
        : "+f"(c[0]), "+f"(c[1]), "+f"(c[2]), "+f"(c[3])
        : "r"(a[0]), "r"(a[1]), "r"(a[2]), "r"(a[3]), "r"(b[0]), "r"(b[1]));
}

__device__ __forceinline__ uint2 pack_h4(float a, float b, float cc, float d) {
    __half2 h01 = __floats2half2_rn(a, b);
    __half2 h23 = __floats2half2_rn(cc, d);
    uint2 pk;
    pk.x = *reinterpret_cast<const uint32_t*>(&h01);
    pk.y = *reinterpret_cast<const uint32_t*>(&h23);
    return pk;
}

// ---------------------------------------------------------------------------
// Kernel 1 (merged prep):
//  blocks [0, WBLOCKS): fold W' = W + down@up -> fp16, 8 rows per block
//    ('up' L2 traffic halved vs 4 rows; all accesses lane-coalesced;
//     per-element FMA order identical to R15 -> bit-identical g_wh)
//  blocks [WBLOCKS, +XBLOCKS): convert x -> fp16, 4 float4 per thread with
//    block-strided indexing (lane-consecutive 16B, R15 proven)
// ---------------------------------------------------------------------------
static constexpr int WROWS   = 8;
static constexpr int WBLOCKS = Ntot / WROWS;                     // 512
static constexpr int XF4     = 4;                                // float4s/thread
static constexpr int XBLOCKS = (Mtot * Ktot / 4) / (1024 * XF4); // 2048

__global__ __launch_bounds__(1024, 1)
void prep_kernel(const float* __restrict__ W,
                 const float* __restrict__ down,
                 const float* __restrict__ up,
                 const float* __restrict__ x) {
    if (blockIdx.x < (unsigned)WBLOCKS) {
        __shared__ float d_s[WROWS * RANK];
        const int o0 = blockIdx.x * WROWS;
        const int i4 = threadIdx.x;  // float4 column index, 0..1023

        if (threadIdx.x < WROWS * RANK)
            d_s[threadIdx.x] = down[o0 * RANK + threadIdx.x];
        __syncthreads();

        float4 acc[WROWS];
#pragma unroll
        for (int j = 0; j < WROWS; j++)
            acc[j] = reinterpret_cast<const float4*>(W + (size_t)(o0 + j) * Ktot)[i4];

#pragma unroll 4
        for (int r = 0; r < RANK; r++) {
            float4 u = reinterpret_cast<const float4*>(up + (size_t)r * Ktot)[i4];
#pragma unroll
            for (int j = 0; j < WROWS; j++) {
                const float dj = d_s[j * RANK + r];
                acc[j].x = fmaf(dj, u.x, acc[j].x);
                acc[j].y = fmaf(dj, u.y, acc[j].y);
                acc[j].z = fmaf(dj, u.z, acc[j].z);
                acc[j].w = fmaf(dj, u.w, acc[j].w);
            }
        }
#pragma unroll
        for (int j = 0; j < WROWS; j++)
            *reinterpret_cast<uint2*>(g_wh + (size_t)(o0 + j) * Ktot + (size_t)i4 * 4) =
                pack_h4(acc[j].x, acc[j].y, acc[j].z, acc[j].w);
    } else {
        // Block covers 1024*XF4 float4s; thread t handles base+t+j*1024.
        const size_t base = (size_t)(blockIdx.x - WBLOCKS) * (1024 * XF4)
                          + threadIdx.x;
        float4 v[XF4];
#pragma unroll
        for (int j = 0; j < XF4; j++)
            v[j] = reinterpret_cast<const float4*>(x)[base + (size_t)j * 1024];
        uint2 pk[XF4];
#pragma unroll
        for (int j = 0; j < XF4; j++)
            pk[j] = pack_h4(v[j].x, v[j].y, v[j].z, v[j].w);
#pragma unroll
        for (int j = 0; j < XF4; j++)
            *reinterpret_cast<uint2*>(g_xh + (base + (size_t)j * 1024) * 4) = pk[j];
    }
}

// ---------------------------------------------------------------------------
// Kernel 2 (R9 best, byte-identical, frozen): persistent-stream GEMM.
// Each CTA owns tiles cta, cta+grid, ... through one continuous TMA ring.
// ---------------------------------------------------------------------------
__global__ __launch_bounds__(256, 1)
void lora_gemm_hmma(const __grid_constant__ CUtensorMap tmap_x,
                    const __grid_constant__ CUtensorMap tmap_w,
                    const float* __restrict__ bias,
                    float* __restrict__ out)
{
    extern __shared__ char smraw[];
    const uint32_t raw  = s2u(smraw);
    const uint32_t base = (raw + 1023u) & ~1023u;

    const uint32_t mb_full  = base;        // 4 x 8B
    const uint32_t mb_empty = base + 64;   // 4 x 8B
    const uint32_t tiles    = base + 1024;

    const int tid  = threadIdx.x;
    const int wid  = tid >> 5;
    const int lane = tid & 31;
    const int cta   = blockIdx.x;
    const int gridn = gridDim.x;
    const int warp_m = wid >> 1;   // 0..3 -> 64 rows each
    const int warp_n = wid & 1;    // 0..1 -> 64 cols each

    int nt = 0;
    for (int t = cta; t < NTILES; t += gridn) nt++;
    const int total_steps = nt * KSTEPS;

    if (tid == 0) {
        for (int s = 0; s < STAGES; s++) {
            MBAR_INIT(mb_full  + 8 * s, 1);
            MBAR_INIT(mb_empty + 8 * s, 8);   // one arrive per warp
        }
    }
    __syncthreads();

    // Prologue: issue global steps 0..STAGES-2 of this CTA's stream
    if (tid == 0) {
#pragma unroll
        for (int p = 0; p < STAGES - 1; p++) {
            if (p < total_steps) {
                const int kt = p >> 6;
                const int t  = cta + kt * gridn;
                const int s  = p & (KSTEPS - 1);
                MBAR_EXPECT_TX(mb_full + 8 * p, (uint32_t)STAGE_BYTES);
                const uint32_t sa = tiles + p * STAGE_BYTES;
                TMA2D(sa,           &tmap_x, s * BK, (t >> 5) * BM, mb_full + 8 * p);
                TMA2D(sa + A_BYTES, &tmap_w, s * BK, (t & 31) * BN, mb_full + 8 * p);
            }
        }
    }

    // Per-lane smem addressing (SW128: XOR const = (row&7)<<4, rows are 128B)
    const int lr16 = lane & 15;
    const int ahi  = (lane >> 4) << 4;            // A col byte offset: 0 / 16
    uint32_t a_off[4], a_xor[4];
#pragma unroll
    for (int mi = 0; mi < 4; mi++) {
        const int r = warp_m * 64 + mi * 16 + lr16;
        a_off[mi] = (uint32_t)r * 128;
        a_xor[mi] = (uint32_t)((r & 7) << 4);
    }
    const int brlo = (lane & 7) + ((lane >> 4) << 3);  // B row-in-16
    const int bhi  = ((lane >> 3) & 1) << 4;           // B col byte: 0 / 16
    uint32_t b_off[4], b_xor[4];
#pragma unroll
    for (int nj = 0; nj < 4; nj++) {
        const int r = warp_n * 64 + nj * 16 + brlo;
        b_off[nj] = (uint32_t)r * 128;
        b_xor[nj] = (uint32_t)((r & 7) << 4);
    }

    const int gid = lane >> 2;
    const int qid = lane & 3;

    int slot = 0, phase = 0;   // consumer ring cursor, continuous across tiles
    int g = 0;                 // consumer global step

    for (int kt = 0; kt < nt; kt++) {
        const int t  = cta + kt * gridn;
        const int bm = (t >> 5) * BM;
        const int bn = (t & 31) * BN;

        float c[4][8][4];
#pragma unroll
        for (int i = 0; i < 4; i++)
#pragma unroll
            for (int j = 0; j < 8; j++)
#pragma unroll
                for (int k = 0; k < 4; k++) c[i][j][k] = 0.0f;

        for (int s = 0; s < KSTEPS; s++) {
            // Producer: issue global step p = g + STAGES-1 (crosses tile bounds)
            if (tid == 0) {
                const int p = g + STAGES - 1;
                if (p < total_steps) {
                    const int ps = p & (STAGES - 1);
                    if (p >= STAGES) MBAR_WAIT(mb_empty + 8 * ps, ((p >> 2) - 1) & 1);
                    const int pk = p >> 6;
                    const int pt = cta + pk * gridn;
                    const int psl = p & (KSTEPS - 1);
                    MBAR_EXPECT_TX(mb_full + 8 * ps, (uint32_t)STAGE_BYTES);
                    const uint32_t sa = tiles + ps * STAGE_BYTES;
                    TMA2D(sa,           &tmap_x, psl * BK, (pt >> 5) * BM, mb_full + 8 * ps);
                    TMA2D(sa + A_BYTES, &tmap_w, psl * BK, (pt & 31) * BN, mb_full + 8 * ps);
                }
            }

            MBAR_WAIT(mb_full + 8 * slot, phase);
            const uint32_t aT = tiles + slot * STAGE_BYTES;
            const uint32_t bT = aT + A_BYTES;

#pragma unroll
            for (int ks = 0; ks < 4; ks++) {
                uint32_t a[4][4], b[4][4];
                const uint32_t acol = (uint32_t)(ks * 32 + ahi);
                const uint32_t bcol = (uint32_t)(ks * 32 + bhi);
#pragma unroll
                for (int mi = 0; mi < 4; mi++)
                    ldsm4(a[mi], aT + a_off[mi] + (acol ^ a_xor[mi]));
#pragma unroll
                for (int nj = 0; nj < 4; nj++)
                    ldsm4(b[nj], bT + b_off[nj] + (bcol ^ b_xor[nj]));
#pragma unroll
                for (int mi = 0; mi < 4; mi++)
#pragma unroll
                    for (int nj = 0; nj < 8; nj++)
                        mma16816(c[mi][nj], a[mi], &b[nj >> 1][(nj & 1) * 2]);
            }

            if (lane == 0) MBAR_ARRIVE(mb_empty + 8 * slot);
            if (++slot == STAGES) { slot = 0; phase ^= 1; }
            g++;
        }

        // Epilogue for tile t (next tile's stages already landing in the ring)
#pragma unroll
        for (int nj = 0; nj < 8; nj++) {
            const int col = bn + warp_n * 64 + nj * 8 + qid * 2;
            const float b0 = __ldg(bias + col);
            const float b1 = __ldg(bias + col + 1);
#pragma unroll
            for (int mi = 0; mi < 4; mi++) {
                const int row = bm + warp_m * 64 + mi * 16 + gid;
                float2 v0 = make_float2(c[mi][nj][0] + b0, c[mi][nj][1] + b1);
                float2 v1 = make_float2(c[mi][nj][2] + b0, c[mi][nj][3] + b1);
                *reinterpret_cast<float2*>(out + (size_t)row * Ntot + col)       = v0;
                *reinterpret_cast<float2*>(out + (size_t)(row + 8) * Ntot + col) = v1;
            }
        }
    }
}

// ---------------------------------------------------------------------------
// Host launch
// ---------------------------------------------------------------------------
typedef CUresult (*EncodeTiledFn)(
    CUtensorMap*, CUtensorMapDataType, cuuint32_t, void*,
    const cuuint64_t*, const cuuint64_t*, const cuuint32_t*, const cuuint32_t*,
    CUtensorMapInterleave, CUtensorMapSwizzle, CUtensorMapL2promotion,
    CUtensorMapFloatOOBfill);

extern "C" void kernel_launch(void* const* d_in, const int* in_sizes, int n_in,
                              void* d_out, int out_size) {
    const float* x    = (const float*)d_in[0];  // [8192, 4096]
    const float* W    = (const float*)d_in[1];  // [4096, 4096]
    const float* bias = (const float*)d_in[2];  // [4096]
    const float* down = (const float*)d_in[3];  // [4096, 16]
    const float* up   = (const float*)d_in[4];  // [16, 4096]
    float* out = (float*)d_out;                 // [8192, 4096]
    (void)in_sizes; (void)n_in; (void)out_size;

    static EncodeTiledFn enc = nullptr;
    if (!enc) {
        void* p = nullptr;
        cudaDriverEntryPointQueryResult qr;
        cudaGetDriverEntryPointByVersion("cuTensorMapEncodeTiled", &p, 12000,
                                         cudaEnableDefault, &qr);
        enc = (EncodeTiledFn)p;
    }
    void* xh_ptr = nullptr, *wh_ptr = nullptr;
    cudaGetSymbolAddress(&xh_ptr, g_xh);
    cudaGetSymbolAddress(&wh_ptr, g_wh);

    static int nsm = 0;
    if (!nsm) {
        cudaDeviceGetAttribute(&nsm, cudaDevAttrMultiProcessorCount, 0);
        if (nsm <= 0) nsm = 148;
    }

    CUtensorMap mx, mw;
    {
        cuuint64_t dims[2]    = {(cuuint64_t)Ktot, (cuuint64_t)Mtot};
        cuuint64_t strides[1] = {(cuuint64_t)Ktot * 2};
        cuuint32_t box[2]     = {(cuuint32_t)BK, (cuuint32_t)BM};
        cuuint32_t es[2]      = {1, 1};
        enc(&mx, CU_TENSOR_MAP_DATA_TYPE_FLOAT16, 2, xh_ptr,
            dims, strides, box, es,
            CU_TENSOR_MAP_INTERLEAVE_NONE, CU_TENSOR_MAP_SWIZZLE_128B,
            CU_TENSOR_MAP_L2_PROMOTION_L2_128B, CU_TENSOR_MAP_FLOAT_OOB_FILL_NONE);

        dims[1] = (cuuint64_t)Ntot;
        box[1]  = (cuuint32_t)BN;
        enc(&mw, CU_TENSOR_MAP_DATA_TYPE_FLOAT16, 2, wh_ptr,
            dims, strides, box, es,
            CU_TENSOR_MAP_INTERLEAVE_NONE, CU_TENSOR_MAP_SWIZZLE_128B,
            CU_TENSOR_MAP_L2_PROMOTION_L2_128B, CU_TENSOR_MAP_FLOAT_OOB_FILL_NONE);
    }

    cudaFuncSetAttribute(lora_gemm_hmma,
                         cudaFuncAttributeMaxDynamicSharedMemorySize, SMEM_ALLOC);

    prep_kernel<<<WBLOCKS + XBLOCKS, 1024>>>(W, down, up, x);

    const int gemm_grid = (NTILES < nsm) ? NTILES : nsm;
    lora_gemm_hmma<<<gemm_grid, 256, SMEM_ALLOC>>>(mx, mw, bias, out);
}

// round 17
// speedup vs baseline: 1.0364x; 1.0364x over previous
#include <cuda_runtime.h>
#include <cuda.h>
#include <cuda_fp16.h>
#include <cstdint>
#include <cstddef>

// ---------------------------------------------------------------------------
// Problem shape (fixed by dataset)
// ---------------------------------------------------------------------------
static constexpr int Mtot = 8192;   // B*S
static constexpr int Ntot = 4096;   // OUT
static constexpr int Ktot = 4096;   // IN
static constexpr int RANK = 16;

// GEMM tiling: CTA 256x128x64, 8 warps (4Mx2N), warp tile 64x64 (R9 config).
static constexpr int BM = 256;
static constexpr int BN = 128;
static constexpr int BK = 64;               // 64 fp16 = 128B row = SW128 atom
static constexpr int KSTEPS = Ktot / BK;    // 64
static constexpr int STAGES = 4;
static constexpr int NTILES = (Mtot / BM) * (Ntot / BN);   // 32*32 = 1024

static constexpr int A_BYTES = BM * BK * 2;            // 32 KB
static constexpr int B_BYTES = BN * BK * 2;            // 16 KB
static constexpr int STAGE_BYTES = A_BYTES + B_BYTES;  // 48 KB
static constexpr int SMEM_ALLOC = 2048 + STAGES * STAGE_BYTES;  // 198656 B

// fp16 scratch: W' = W + down@up, and x converted
__device__ __align__(1024) __half g_wh[(size_t)Ntot * Ktot];
__device__ __align__(1024) __half g_xh[(size_t)Mtot * Ktot];

// ---------------------------------------------------------------------------
// PTX helpers (non-'a' instructions only: sm_90 TMA + sm_80 mma)
// ---------------------------------------------------------------------------
__device__ __forceinline__ uint32_t s2u(const void* p) {
    uint32_t a;
    asm("{ .reg .u64 t; cvta.to.shared.u64 t, %1; cvt.u32.u64 %0, t; }"
        : "=r"(a) : "l"(p));
    return a;
}

#define MBAR_INIT(addr, cnt) \
    asm volatile("mbarrier.init.shared.b64 [%0], %1;" :: "r"(addr), "r"(cnt) : "memory")

#define MBAR_EXPECT_TX(addr, bytes) \
    asm volatile("mbarrier.arrive.expect_tx.shared.b64 _, [%0], %1;" \
                 :: "r"(addr), "r"(bytes) : "memory")

#define MBAR_ARRIVE(addr) \
    asm volatile("mbarrier.arrive.shared.b64 _, [%0];" :: "r"(addr) : "memory")

#define MBAR_WAIT(addr, parity) do {                                          \
    uint32_t _mb = (addr); uint32_t _ph = (parity); uint32_t _done;           \
    asm volatile("{\n\t.reg .pred p;\n\t"                                     \
        "mbarrier.try_wait.parity.acquire.cta.shared::cta.b64 p, [%1], %2;\n\t" \
        "selp.b32 %0, 1, 0, p;\n\t}"                                          \
        : "=r"(_done) : "r"(_mb), "r"(_ph) : "memory");                       \
    if (!_done) {                                                             \
        asm volatile("{\n\t.reg .pred P1;\n\t"                                \
            "WL_%=:\n\t"                                                      \
            "mbarrier.try_wait.parity.acquire.cta.shared::cta.b64 P1, [%0], %1, 0x989680;\n\t" \
            "@P1 bra.uni WD_%=;\n\t"                                          \
            "bra.uni WL_%=;\n\t"                                              \
            "WD_%=:\n\t}" :: "r"(_mb), "r"(_ph) : "memory");                  \
    }                                                                         \
} while (0)

#define TMA2D(dst, map, cx, cy, mbar)                                         \
    asm volatile("cp.async.bulk.tensor.2d.shared::cta.global.tile"            \
                 ".mbarrier::complete_tx::bytes [%0], [%1, {%2, %3}], [%4];"  \
                 :: "r"(dst), "l"(map), "r"(cx), "r"(cy), "r"(mbar) : "memory")

__device__ __forceinline__ void ldsm4(uint32_t* r, uint32_t addr) {
    asm volatile("ldmatrix.sync.aligned.m8n8.x4.shared.b16 {%0,%1,%2,%3}, [%4];"
                 : "=r"(r[0]), "=r"(r[1]), "=r"(r[2]), "=r"(r[3]) : "r"(addr));
}

__device__ __forceinline__ void mma16816(float* c, const uint32_t* a, const uint32_t* b) {
    asm volatile(
        "mma.sync.aligned.m16n8k16.row.col.f32.f16.f16.f32 "
        "{%0,%1,%2,%3}, {%4,%5,%6,%7}, {%8,%9}, {%0,%1,%2,%3};"
        : "+f"(c[0]), "+f"(c[1]), "+f"(c[2]), "+f"(c[3])
        : "r"(a[0]), "r"(a[1]), "r"(a[2]), "r"(a[3]), "r"(b[0]), "r"(b[1]));
}

__device__ __forceinline__ uint2 pack_h4(float a, float b, float cc, float d) {
    __half2 h01 = __floats2half2_rn(a, b);
    __half2 h23 = __floats2half2_rn(cc, d);
    uint2 pk;
    pk.x = *reinterpret_cast<const uint32_t*>(&h01);
    pk.y = *reinterpret_cast<const uint32_t*>(&h23);
    return pk;
}

// ---------------------------------------------------------------------------
// Kernel 1 (merged prep, R15 structure; x-path MLP raised to 8):
//  blocks [0, WBLOCKS): fold W' = W + down@up -> fp16, 4 rows per block
//    (R15 proven: lane-coalesced, acc[4] keeps regs low -> MLP high)
//  blocks [WBLOCKS, +XBLOCKS): convert x -> fp16, 8 float4 per thread with
//    BLOCK-STRIDED indexing (base + tid + j*1024): lane-consecutive 16B,
//    8 outstanding loads per thread (regs ~52 < 64-cap).
// ---------------------------------------------------------------------------
static constexpr int WROWS   = 4;
static constexpr int WBLOCKS = Ntot / WROWS;                     // 1024
static constexpr int XF4     = 8;                                // float4s/thread
static constexpr int XBLOCKS = (Mtot * Ktot / 4) / (1024 * XF4); // 1024

__global__ __launch_bounds__(1024, 1)
void prep_kernel(const float* __restrict__ W,
                 const float* __restrict__ down,
                 const float* __restrict__ up,
                 const float* __restrict__ x) {
    if (blockIdx.x < (unsigned)WBLOCKS) {
        __shared__ float d_s[WROWS * RANK];
        const int o0 = blockIdx.x * WROWS;
        const int i4 = threadIdx.x;  // float4 column index, 0..1023

        if (threadIdx.x < WROWS * RANK)
            d_s[threadIdx.x] = down[o0 * RANK + threadIdx.x];
        __syncthreads();

        float4 acc[WROWS];
#pragma unroll
        for (int j = 0; j < WROWS; j++)
            acc[j] = reinterpret_cast<const float4*>(W + (size_t)(o0 + j) * Ktot)[i4];

#pragma unroll 4
        for (int r = 0; r < RANK; r++) {
            float4 u = reinterpret_cast<const float4*>(up + (size_t)r * Ktot)[i4];
#pragma unroll
            for (int j = 0; j < WROWS; j++) {
                const float dj = d_s[j * RANK + r];
                acc[j].x = fmaf(dj, u.x, acc[j].x);
                acc[j].y = fmaf(dj, u.y, acc[j].y);
                acc[j].z = fmaf(dj, u.z, acc[j].z);
                acc[j].w = fmaf(dj, u.w, acc[j].w);
            }
        }
#pragma unroll
        for (int j = 0; j < WROWS; j++)
            *reinterpret_cast<uint2*>(g_wh + (size_t)(o0 + j) * Ktot + (size_t)i4 * 4) =
                pack_h4(acc[j].x, acc[j].y, acc[j].z, acc[j].w);
    } else {
        // Block covers 1024*XF4 float4s; thread t handles base+t+j*1024.
        const size_t base = (size_t)(blockIdx.x - WBLOCKS) * (1024 * XF4)
                          + threadIdx.x;
        float4 v[XF4];
#pragma unroll
        for (int j = 0; j < XF4; j++)
            v[j] = reinterpret_cast<const float4*>(x)[base + (size_t)j * 1024];
        uint2 pk[XF4];
#pragma unroll
        for (int j = 0; j < XF4; j++)
            pk[j] = pack_h4(v[j].x, v[j].y, v[j].z, v[j].w);
#pragma unroll
        for (int j = 0; j < XF4; j++)
            *reinterpret_cast<uint2*>(g_xh + (base + (size_t)j * 1024) * 4) = pk[j];
    }
}

// ---------------------------------------------------------------------------
// Kernel 2 (R9 best, byte-identical, frozen): persistent-stream GEMM.
// Each CTA owns tiles cta, cta+grid, ... through one continuous TMA ring.
// ---------------------------------------------------------------------------
__global__ __launch_bounds__(256, 1)
void lora_gemm_hmma(const __grid_constant__ CUtensorMap tmap_x,
                    const __grid_constant__ CUtensorMap tmap_w,
                    const float* __restrict__ bias,
                    float* __restrict__ out)
{
    extern __shared__ char smraw[];
    const uint32_t raw  = s2u(smraw);
    const uint32_t base = (raw + 1023u) & ~1023u;

    const uint32_t mb_full  = base;        // 4 x 8B
    const uint32_t mb_empty = base + 64;   // 4 x 8B
    const uint32_t tiles    = base + 1024;

    const int tid  = threadIdx.x;
    const int wid  = tid >> 5;
    const int lane = tid & 31;
    const int cta   = blockIdx.x;
    const int gridn = gridDim.x;
    const int warp_m = wid >> 1;   // 0..3 -> 64 rows each
    const int warp_n = wid & 1;    // 0..1 -> 64 cols each

    int nt = 0;
    for (int t = cta; t < NTILES; t += gridn) nt++;
    const int total_steps = nt * KSTEPS;

    if (tid == 0) {
        for (int s = 0; s < STAGES; s++) {
            MBAR_INIT(mb_full  + 8 * s, 1);
            MBAR_INIT(mb_empty + 8 * s, 8);   // one arrive per warp
        }
    }
    __syncthreads();

    // Prologue: issue global steps 0..STAGES-2 of this CTA's stream
    if (tid == 0) {
#pragma unroll
        for (int p = 0; p < STAGES - 1; p++) {
            if (p < total_steps) {
                const int kt = p >> 6;
                const int t  = cta + kt * gridn;
                const int s  = p & (KSTEPS - 1);
                MBAR_EXPECT_TX(mb_full + 8 * p, (uint32_t)STAGE_BYTES);
                const uint32_t sa = tiles + p * STAGE_BYTES;
                TMA2D(sa,           &tmap_x, s * BK, (t >> 5) * BM, mb_full + 8 * p);
                TMA2D(sa + A_BYTES, &tmap_w, s * BK, (t & 31) * BN, mb_full + 8 * p);
            }
        }
    }

    // Per-lane smem addressing (SW128: XOR const = (row&7)<<4, rows are 128B)
    const int lr16 = lane & 15;
    const int ahi  = (lane >> 4) << 4;            // A col byte offset: 0 / 16
    uint32_t a_off[4], a_xor[4];
#pragma unroll
    for (int mi = 0; mi < 4; mi++) {
        const int r = warp_m * 64 + mi * 16 + lr16;
        a_off[mi] = (uint32_t)r * 128;
        a_xor[mi] = (uint32_t)((r & 7) << 4);
    }
    const int brlo = (lane & 7) + ((lane >> 4) << 3);  // B row-in-16
    const int bhi  = ((lane >> 3) & 1) << 4;           // B col byte: 0 / 16
    uint32_t b_off[4], b_xor[4];
#pragma unroll
    for (int nj = 0; nj < 4; nj++) {
        const int r = warp_n * 64 + nj * 16 + brlo;
        b_off[nj] = (uint32_t)r * 128;
        b_xor[nj] = (uint32_t)((r & 7) << 4);
    }

    const int gid = lane >> 2;
    const int qid = lane & 3;

    int slot = 0, phase = 0;   // consumer ring cursor, continuous across tiles
    int g = 0;                 // consumer global step

    for (int kt = 0; kt < nt; kt++) {
        const int t  = cta + kt * gridn;
        const int bm = (t >> 5) * BM;
        const int bn = (t & 31) * BN;

        float c[4][8][4];
#pragma unroll
        for (int i = 0; i < 4; i++)
#pragma unroll
            for (int j = 0; j < 8; j++)
#pragma unroll
                for (int k = 0; k < 4; k++) c[i][j][k] = 0.0f;

        for (int s = 0; s < KSTEPS; s++) {
            // Producer: issue global step p = g + STAGES-1 (crosses tile bounds)
            if (tid == 0) {
                const int p = g + STAGES - 1;
                if (p < total_steps) {
                    const int ps = p & (STAGES - 1);
                    if (p >= STAGES) MBAR_WAIT(mb_empty + 8 * ps, ((p >> 2) - 1) & 1);
                    const int pk = p >> 6;
                    const int pt = cta + pk * gridn;
                    const int psl = p & (KSTEPS - 1);
                    MBAR_EXPECT_TX(mb_full + 8 * ps, (uint32_t)STAGE_BYTES);
                    const uint32_t sa = tiles + ps * STAGE_BYTES;
                    TMA2D(sa,           &tmap_x, psl * BK, (pt >> 5) * BM, mb_full + 8 * ps);
                    TMA2D(sa + A_BYTES, &tmap_w, psl * BK, (pt & 31) * BN, mb_full + 8 * ps);
                }
            }

            MBAR_WAIT(mb_full + 8 * slot, phase);
            const uint32_t aT = tiles + slot * STAGE_BYTES;
            const uint32_t bT = aT + A_BYTES;

#pragma unroll
            for (int ks = 0; ks < 4; ks++) {
                uint32_t a[4][4], b[4][4];
                const uint32_t acol = (uint32_t)(ks * 32 + ahi);
                const uint32_t bcol = (uint32_t)(ks * 32 + bhi);
#pragma unroll
                for (int mi = 0; mi < 4; mi++)
                    ldsm4(a[mi], aT + a_off[mi] + (acol ^ a_xor[mi]));
#pragma unroll
                for (int nj = 0; nj < 4; nj++)
                    ldsm4(b[nj], bT + b_off[nj] + (bcol ^ b_xor[nj]));
#pragma unroll
                for (int mi = 0; mi < 4; mi++)
#pragma unroll
                    for (int nj = 0; nj < 8; nj++)
                        mma16816(c[mi][nj], a[mi], &b[nj >> 1][(nj & 1) * 2]);
            }

            if (lane == 0) MBAR_ARRIVE(mb_empty + 8 * slot);
            if (++slot == STAGES) { slot = 0; phase ^= 1; }
            g++;
        }

        // Epilogue for tile t (next tile's stages already landing in the ring)
#pragma unroll
        for (int nj = 0; nj < 8; nj++) {
            const int col = bn + warp_n * 64 + nj * 8 + qid * 2;
            const float b0 = __ldg(bias + col);
            const float b1 = __ldg(bias + col + 1);
#pragma unroll
            for (int mi = 0; mi < 4; mi++) {
                const int row = bm + warp_m * 64 + mi * 16 + gid;
                float2 v0 = make_float2(c[mi][nj][0] + b0, c[mi][nj][1] + b1);
                float2 v1 = make_float2(c[mi][nj][2] + b0, c[mi][nj][3] + b1);
                *reinterpret_cast<float2*>(out + (size_t)row * Ntot + col)       = v0;
                *reinterpret_cast<float2*>(out + (size_t)(row + 8) * Ntot + col) = v1;
            }
        }
    }
}

// ---------------------------------------------------------------------------
// Host launch
// ---------------------------------------------------------------------------
typedef CUresult (*EncodeTiledFn)(
    CUtensorMap*, CUtensorMapDataType, cuuint32_t, void*,
    const cuuint64_t*, const cuuint64_t*, const cuuint32_t*, const cuuint32_t*,
    CUtensorMapInterleave, CUtensorMapSwizzle, CUtensorMapL2promotion,
    CUtensorMapFloatOOBfill);

extern "C" void kernel_launch(void* const* d_in, const int* in_sizes, int n_in,
                              void* d_out, int out_size) {
    const float* x    = (const float*)d_in[0];  // [8192, 4096]
    const float* W    = (const float*)d_in[1];  // [4096, 4096]
    const float* bias = (const float*)d_in[2];  // [4096]
    const float* down = (const float*)d_in[3];  // [4096, 16]
    const float* up   = (const float*)d_in[4];  // [16, 4096]
    float* out = (float*)d_out;                 // [8192, 4096]
    (void)in_sizes; (void)n_in; (void)out_size;

    static EncodeTiledFn enc = nullptr;
    if (!enc) {
        void* p = nullptr;
        cudaDriverEntryPointQueryResult qr;
        cudaGetDriverEntryPointByVersion("cuTensorMapEncodeTiled", &p, 12000,
                                         cudaEnableDefault, &qr);
        enc = (EncodeTiledFn)p;
    }
    void* xh_ptr = nullptr, *wh_ptr = nullptr;
    cudaGetSymbolAddress(&xh_ptr, g_xh);
    cudaGetSymbolAddress(&wh_ptr, g_wh);

    static int nsm = 0;
    if (!nsm) {
        cudaDeviceGetAttribute(&nsm, cudaDevAttrMultiProcessorCount, 0);
        if (nsm <= 0) nsm = 148;
    }

    CUtensorMap mx, mw;
    {
        cuuint64_t dims[2]    = {(cuuint64_t)Ktot, (cuuint64_t)Mtot};
        cuuint64_t strides[1] = {(cuuint64_t)Ktot * 2};
        cuuint32_t box[2]     = {(cuuint32_t)BK, (cuuint32_t)BM};
        cuuint32_t es[2]      = {1, 1};
        enc(&mx, CU_TENSOR_MAP_DATA_TYPE_FLOAT16, 2, xh_ptr,
            dims, strides, box, es,
            CU_TENSOR_MAP_INTERLEAVE_NONE, CU_TENSOR_MAP_SWIZZLE_128B,
            CU_TENSOR_MAP_L2_PROMOTION_L2_128B, CU_TENSOR_MAP_FLOAT_OOB_FILL_NONE);

        dims[1] = (cuuint64_t)Ntot;
        box[1]  = (cuuint32_t)BN;
        enc(&mw, CU_TENSOR_MAP_DATA_TYPE_FLOAT16, 2, wh_ptr,
            dims, strides, box, es,
            CU_TENSOR_MAP_INTERLEAVE_NONE, CU_TENSOR_MAP_SWIZZLE_128B,
            CU_TENSOR_MAP_L2_PROMOTION_L2_128B, CU_TENSOR_MAP_FLOAT_OOB_FILL_NONE);
    }

    cudaFuncSetAttribute(lora_gemm_hmma,
                         cudaFuncAttributeMaxDynamicSharedMemorySize, SMEM_ALLOC);

    prep_kernel<<<WBLOCKS + XBLOCKS, 1024>>>(W, down, up, x);

    const int gemm_grid = (NTILES < nsm) ? NTILES : nsm;
    lora_gemm_hmma<<<gemm_grid, 256, SMEM_ALLOC>>>(mx, mw, bias, out);
}